// round 3
// baseline (speedup 1.0000x reference)
#include <cuda_runtime.h>
#include <math.h>

// MinDistLoss: out = min_{b,n,m} sqrt(max( xx[b,n] + yy[b,m] - 2*dot(v1[b,n],v2[b,m]), 0 ))
//
// FROZEN numeric scheme (bit-exact vs reference, rel_err = 0.0 since round 1):
//   xx = (x0*x0 + x1*x1) + x2*x2         (separate mul/add)
//   dot = fma(z,z', fma(y,y', x*x'))     (ascending fma chain)
//   sq = fma(-2, dot, xx+yy)
// f32x2 packed ops round each half identically to scalar -> numerics unchanged.
// Single fused kernel: per-block atomicMin + last-block finalize (sqrt + reset).

#define TN 128
#define TM 256
#define THREADS 256
#define FLT_MAX_BITS 0x7f7fffffu

__device__ unsigned g_minbits = FLT_MAX_BITS;
__device__ unsigned g_count   = 0;

typedef unsigned long long u64;

__device__ __forceinline__ u64 pack2(float lo, float hi) {
    u64 r; asm("mov.b64 %0, {%1, %2};" : "=l"(r) : "f"(lo), "f"(hi)); return r;
}
__device__ __forceinline__ void unpack2(u64 v, float& lo, float& hi) {
    asm("mov.b64 {%0, %1}, %2;" : "=f"(lo), "=f"(hi) : "l"(v));
}
__device__ __forceinline__ u64 mul2(u64 a, u64 b) {
    u64 r; asm("mul.rn.f32x2 %0, %1, %2;" : "=l"(r) : "l"(a), "l"(b)); return r;
}
__device__ __forceinline__ u64 add2(u64 a, u64 b) {
    u64 r; asm("add.rn.f32x2 %0, %1, %2;" : "=l"(r) : "l"(a), "l"(b)); return r;
}
__device__ __forceinline__ u64 fma2(u64 a, u64 b, u64 c) {
    u64 r; asm("fma.rn.f32x2 %0, %1, %2, %3;" : "=l"(r) : "l"(a), "l"(b), "l"(c)); return r;
}

__global__ __launch_bounds__(THREADS)
void pairmin_kernel(const float* __restrict__ v1, const float* __restrict__ v2,
                    int B, int N, int M, int nblocks, float* __restrict__ out) {
    // a-side: duplicated {v,v} pairs.  b-side: natural {m, m+1} pairs.
    __shared__ u64 sax[TN], say[TN], saz[TN], saw[TN];
    __shared__ u64 sbx[TM / 2], sby[TM / 2], sbz[TM / 2], sbw[TM / 2];

    const int b  = blockIdx.z;
    const int n0 = blockIdx.y * TN;
    const int m0 = blockIdx.x * TM;
    const float* p1 = v1 + (size_t)b * N * 3;
    const float* p2 = v2 + (size_t)b * M * 3;
    const int tid = threadIdx.x;

    // Stage n-tile (clamped indices: duplicate pairs harmless under min)
    if (tid < TN) {
        int n = n0 + tid; if (n > N - 1) n = N - 1;
        float x0 = p1[n * 3 + 0], x1 = p1[n * 3 + 1], x2 = p1[n * 3 + 2];
        float w = __fadd_rn(__fadd_rn(__fmul_rn(x0, x0), __fmul_rn(x1, x1)),
                            __fmul_rn(x2, x2));
        sax[tid] = pack2(x0, x0); say[tid] = pack2(x1, x1);
        saz[tid] = pack2(x2, x2); saw[tid] = pack2(w, w);
    }
    // Stage m-tile (each thread one m; write scalar halves)
    {
        int m = m0 + tid; if (m > M - 1) m = M - 1;
        float y0 = p2[m * 3 + 0], y1 = p2[m * 3 + 1], y2 = p2[m * 3 + 2];
        float w = __fadd_rn(__fadd_rn(__fmul_rn(y0, y0), __fmul_rn(y1, y1)),
                            __fmul_rn(y2, y2));
        ((float*)sbx)[tid] = y0; ((float*)sby)[tid] = y1;
        ((float*)sbz)[tid] = y2; ((float*)sbw)[tid] = w;
    }
    __syncthreads();

    const int tx = tid & 15;   // b-group: 8 pairs at slots jp*16 + tx (conflict-free)
    const int ty = tid >> 4;   // a-group: 8 n rows ty*8 + i

    u64 bx2[8], by2[8], bz2[8], bw2[8];
#pragma unroll
    for (int jp = 0; jp < 8; jp++) {
        int s = jp * 16 + tx;
        bx2[jp] = sbx[s]; by2[jp] = sby[s]; bz2[jp] = sbz[s]; bw2[jp] = sbw[s];
    }

    const u64 NEG2 = 0xC0000000C0000000ULL;  // {-2.0f, -2.0f}
    float best0 = 3.4028235e38f, best1 = best0, best2 = best0, best3 = best0;

#pragma unroll
    for (int i = 0; i < 8; i++) {
        int n = ty * 8 + i;
        u64 ax = sax[n], ay = say[n], az = saz[n], aw = saw[n];
#pragma unroll
        for (int jp = 0; jp < 8; jp++) {
            u64 d = mul2(ax, bx2[jp]);
            d = fma2(ay, by2[jp], d);
            d = fma2(az, bz2[jp], d);
            u64 t  = add2(aw, bw2[jp]);
            u64 sq = fma2(NEG2, d, t);
            float lo, hi;
            unpack2(sq, lo, hi);
            if (jp & 1) { best1 = fminf(best1, lo); best3 = fminf(best3, hi); }
            else        { best0 = fminf(best0, lo); best2 = fminf(best2, hi); }
        }
    }
    float best = fminf(fminf(best0, best1), fminf(best2, best3));

    // Warp reduce
#pragma unroll
    for (int off = 16; off; off >>= 1)
        best = fminf(best, __shfl_xor_sync(0xffffffffu, best, off));

    __shared__ float wmin[THREADS / 32];
    if ((tid & 31) == 0) wmin[tid >> 5] = best;
    __syncthreads();

    if (tid == 0) {
        float r = wmin[0];
#pragma unroll
        for (int w = 1; w < THREADS / 32; w++) r = fminf(r, wmin[w]);
        // nonneg float bits order as uint
        atomicMin(&g_minbits, __float_as_uint(fmaxf(r, 0.0f)));
        __threadfence();
        unsigned ticket = atomicAdd(&g_count, 1);
        if (ticket == (unsigned)(nblocks - 1)) {
            // last block: read-and-reset (deterministic across graph replays)
            unsigned bits = atomicExch(&g_minbits, FLT_MAX_BITS);
            atomicExch(&g_count, 0u);
            out[0] = sqrtf(__uint_as_float(bits));
        }
    }
}

extern "C" void kernel_launch(void* const* d_in, const int* in_sizes, int n_in,
                              void* d_out, int out_size) {
    const float* v1 = (const float*)d_in[0];
    const float* v2 = (const float*)d_in[1];
    float* out = (float*)d_out;

    const int B = 16;
    const int N = in_sizes[0] / (B * 3);
    const int M = in_sizes[1] / (B * 3);

    dim3 grid((M + TM - 1) / TM, (N + TN - 1) / TN, B);
    int nblocks = (int)(grid.x * grid.y * grid.z);

    pairmin_kernel<<<grid, THREADS>>>(v1, v2, B, N, M, nblocks, out);
}

// round 4
// speedup vs baseline: 1.1151x; 1.1151x over previous
#include <cuda_runtime.h>
#include <math.h>

// MinDistLoss: out = min_{b,n,m} sqrt(max( xx[b,n] + yy[b,m] - 2*dot(v1[b,n],v2[b,m]), 0 ))
//
// FROZEN numeric scheme (bit-exact vs reference, rel_err = 0.0 since round 1):
//   xx = (x0*x0 + x1*x1) + x2*x2         (separate mul/add)
//   dot = fma(z,z', fma(y,y', x*x'))     (ascending fma chain)
//   sq = fma(-2, dot, xx+yy)
// f32x2 packed ops round each half identically to scalar -> numerics unchanged.
//
// R4: occupancy fix. R3 was latency-bound (occ 18.5%, fma 42%): 100 regs -> 2 CTAs/SM.
// Now only b-side lives in regs (32 regs); a-side streamed from smem as
// pre-duplicated {v,v} u64 via LDS.64 broadcast. Target 4 CTAs/SM.

#define TN 128
#define TM 128
#define THREADS 256
#define FLT_MAX_BITS 0x7f7fffffu

__device__ unsigned g_minbits = FLT_MAX_BITS;
__device__ unsigned g_count   = 0;

typedef unsigned long long u64;

__device__ __forceinline__ u64 pack2(float lo, float hi) {
    u64 r; asm("mov.b64 %0, {%1, %2};" : "=l"(r) : "f"(lo), "f"(hi)); return r;
}
__device__ __forceinline__ void unpack2(u64 v, float& lo, float& hi) {
    asm("mov.b64 {%0, %1}, %2;" : "=f"(lo), "=f"(hi) : "l"(v));
}
__device__ __forceinline__ u64 mul2(u64 a, u64 b) {
    u64 r; asm("mul.rn.f32x2 %0, %1, %2;" : "=l"(r) : "l"(a), "l"(b)); return r;
}
__device__ __forceinline__ u64 add2(u64 a, u64 b) {
    u64 r; asm("add.rn.f32x2 %0, %1, %2;" : "=l"(r) : "l"(a), "l"(b)); return r;
}
__device__ __forceinline__ u64 fma2(u64 a, u64 b, u64 c) {
    u64 r; asm("fma.rn.f32x2 %0, %1, %2, %3;" : "=l"(r) : "l"(a), "l"(b), "l"(c)); return r;
}

__global__ __launch_bounds__(THREADS, 4)
void pairmin_kernel(const float* __restrict__ v1, const float* __restrict__ v2,
                    int B, int N, int M, int nblocks, float* __restrict__ out) {
    // a-side: duplicated {v,v} u64.  b-side: natural {m, m+1} u64 pairs.
    __shared__ u64 sax[TN], say[TN], saz[TN], saw[TN];
    __shared__ u64 sbx[TM / 2], sby[TM / 2], sbz[TM / 2], sbw[TM / 2];

    const int b  = blockIdx.z;
    const int n0 = blockIdx.y * TN;
    const int m0 = blockIdx.x * TM;
    const float* p1 = v1 + (size_t)b * N * 3;
    const float* p2 = v2 + (size_t)b * M * 3;
    const int tid = threadIdx.x;

    // Stage n-tile as duplicated pairs (clamped: duplicate pairs harmless under min)
    if (tid < TN) {
        int n = n0 + tid; if (n > N - 1) n = N - 1;
        float x0 = p1[n * 3 + 0], x1 = p1[n * 3 + 1], x2 = p1[n * 3 + 2];
        float w = __fadd_rn(__fadd_rn(__fmul_rn(x0, x0), __fmul_rn(x1, x1)),
                            __fmul_rn(x2, x2));
        sax[tid] = pack2(x0, x0); say[tid] = pack2(x1, x1);
        saz[tid] = pack2(x2, x2); saw[tid] = pack2(w, w);
    }
    // Stage m-tile: write scalar halves of the natural pairs
    if (tid < TM) {
        int m = m0 + tid; if (m > M - 1) m = M - 1;
        float y0 = p2[m * 3 + 0], y1 = p2[m * 3 + 1], y2 = p2[m * 3 + 2];
        float w = __fadd_rn(__fadd_rn(__fmul_rn(y0, y0), __fmul_rn(y1, y1)),
                            __fmul_rn(y2, y2));
        ((float*)sbx)[tid] = y0; ((float*)sby)[tid] = y1;
        ((float*)sbz)[tid] = y2; ((float*)sbw)[tid] = w;
    }
    __syncthreads();

    const int tx = tid & 15;   // b-group: 4 pairs at slots jp*16 + tx (conflict-free)
    const int ty = tid >> 4;   // a-group: 8 n rows ty*8 + i

    // b-side in registers: 4 packed pairs x 4 vars = 32 regs
    u64 bx2[4], by2[4], bz2[4], bw2[4];
#pragma unroll
    for (int jp = 0; jp < 4; jp++) {
        int s = jp * 16 + tx;
        bx2[jp] = sbx[s]; by2[jp] = sby[s]; bz2[jp] = sbz[s]; bw2[jp] = sbw[s];
    }

    const u64 NEG2 = 0xC0000000C0000000ULL;  // {-2.0f, -2.0f}
    float best0 = 3.4028235e38f, best1 = best0, best2 = best0, best3 = best0;

#pragma unroll 2
    for (int i = 0; i < 8; i++) {
        const int n = ty * 8 + i;
        u64 ax = sax[n], ay = say[n], az = saz[n], aw = saw[n];
#pragma unroll
        for (int jp = 0; jp < 4; jp++) {
            u64 d = mul2(ax, bx2[jp]);
            d = fma2(ay, by2[jp], d);
            d = fma2(az, bz2[jp], d);
            u64 t  = add2(aw, bw2[jp]);
            u64 sq = fma2(NEG2, d, t);
            float lo, hi;
            unpack2(sq, lo, hi);
            if (jp & 1) { best1 = fminf(best1, lo); best3 = fminf(best3, hi); }
            else        { best0 = fminf(best0, lo); best2 = fminf(best2, hi); }
        }
    }
    float best = fminf(fminf(best0, best1), fminf(best2, best3));

    // Warp reduce
#pragma unroll
    for (int off = 16; off; off >>= 1)
        best = fminf(best, __shfl_xor_sync(0xffffffffu, best, off));

    __shared__ float wmin[THREADS / 32];
    if ((tid & 31) == 0) wmin[tid >> 5] = best;
    __syncthreads();

    if (tid == 0) {
        float r = wmin[0];
#pragma unroll
        for (int w = 1; w < THREADS / 32; w++) r = fminf(r, wmin[w]);
        // nonneg float bits order as uint
        atomicMin(&g_minbits, __float_as_uint(fmaxf(r, 0.0f)));
        __threadfence();
        unsigned ticket = atomicAdd(&g_count, 1);
        if (ticket == (unsigned)(nblocks - 1)) {
            // last block: read-and-reset (deterministic across graph replays)
            unsigned bits = atomicExch(&g_minbits, FLT_MAX_BITS);
            atomicExch(&g_count, 0u);
            out[0] = sqrtf(__uint_as_float(bits));
        }
    }
}

extern "C" void kernel_launch(void* const* d_in, const int* in_sizes, int n_in,
                              void* d_out, int out_size) {
    const float* v1 = (const float*)d_in[0];
    const float* v2 = (const float*)d_in[1];
    float* out = (float*)d_out;

    const int B = 16;
    const int N = in_sizes[0] / (B * 3);
    const int M = in_sizes[1] / (B * 3);

    dim3 grid((M + TM - 1) / TM, (N + TN - 1) / TN, B);
    int nblocks = (int)(grid.x * grid.y * grid.z);

    pairmin_kernel<<<grid, THREADS>>>(v1, v2, B, N, M, nblocks, out);
}

// round 5
// speedup vs baseline: 1.2515x; 1.1223x over previous
#include <cuda_runtime.h>
#include <math.h>

// MinDistLoss: out = min_{b,n,m} sqrt(max( xx[b,n] + yy[b,m] - 2*dot(v1[b,n],v2[b,m]), 0 ))
//
// FROZEN numeric scheme (bit-exact vs reference, rel_err = 0.0 since round 1):
//   xx = (x0*x0 + x1*x1) + x2*x2         (separate mul/add)
//   dot = fma(z,z', fma(y,y', x*x'))     (ascending fma chain)
//   sq = fma(-2, dot, xx+yy)
// f32x2 packed ops round each half identically to scalar -> numerics unchanged.
//
// R5: amortize per-block overhead. TN=256 (16 n-rows/thread), b-side (4 packed
// m-pairs) in regs, a-side streamed from smem as duplicated {v,v} u64.
// 8 independent min accumulators. Fused atomic-min finalize.

#define TN 256
#define TM 128
#define THREADS 256
#define FLT_MAX_BITS 0x7f7fffffu

__device__ unsigned g_minbits = FLT_MAX_BITS;
__device__ unsigned g_count   = 0;

typedef unsigned long long u64;

__device__ __forceinline__ u64 pack2(float lo, float hi) {
    u64 r; asm("mov.b64 %0, {%1, %2};" : "=l"(r) : "f"(lo), "f"(hi)); return r;
}
__device__ __forceinline__ void unpack2(u64 v, float& lo, float& hi) {
    asm("mov.b64 {%0, %1}, %2;" : "=f"(lo), "=f"(hi) : "l"(v));
}
__device__ __forceinline__ u64 mul2(u64 a, u64 b) {
    u64 r; asm("mul.rn.f32x2 %0, %1, %2;" : "=l"(r) : "l"(a), "l"(b)); return r;
}
__device__ __forceinline__ u64 add2(u64 a, u64 b) {
    u64 r; asm("add.rn.f32x2 %0, %1, %2;" : "=l"(r) : "l"(a), "l"(b)); return r;
}
__device__ __forceinline__ u64 fma2(u64 a, u64 b, u64 c) {
    u64 r; asm("fma.rn.f32x2 %0, %1, %2, %3;" : "=l"(r) : "l"(a), "l"(b), "l"(c)); return r;
}

__global__ __launch_bounds__(THREADS, 4)
void pairmin_kernel(const float* __restrict__ v1, const float* __restrict__ v2,
                    int B, int N, int M, int nblocks, float* __restrict__ out) {
    // a-side: duplicated {v,v} u64.  b-side: natural {m, m+1} u64 pairs.
    __shared__ u64 sax[TN], say[TN], saz[TN], saw[TN];
    __shared__ u64 sbx[TM / 2], sby[TM / 2], sbz[TM / 2], sbw[TM / 2];

    const int b  = blockIdx.z;
    const int n0 = blockIdx.y * TN;
    const int m0 = blockIdx.x * TM;
    const float* p1 = v1 + (size_t)b * N * 3;
    const float* p2 = v2 + (size_t)b * M * 3;
    const int tid = threadIdx.x;

    // Issue all global loads up front (overlap latency), then do norm math.
    int n = n0 + tid; if (n > N - 1) n = N - 1;
    float x0 = p1[n * 3 + 0], x1 = p1[n * 3 + 1], x2 = p1[n * 3 + 2];

    float y0 = 0.f, y1 = 0.f, y2 = 0.f;
    if (tid < TM) {
        int m = m0 + tid; if (m > M - 1) m = M - 1;
        y0 = p2[m * 3 + 0]; y1 = p2[m * 3 + 1]; y2 = p2[m * 3 + 2];
    }

    {
        float w = __fadd_rn(__fadd_rn(__fmul_rn(x0, x0), __fmul_rn(x1, x1)),
                            __fmul_rn(x2, x2));
        sax[tid] = pack2(x0, x0); say[tid] = pack2(x1, x1);
        saz[tid] = pack2(x2, x2); saw[tid] = pack2(w, w);
    }
    if (tid < TM) {
        float w = __fadd_rn(__fadd_rn(__fmul_rn(y0, y0), __fmul_rn(y1, y1)),
                            __fmul_rn(y2, y2));
        ((float*)sbx)[tid] = y0; ((float*)sby)[tid] = y1;
        ((float*)sbz)[tid] = y2; ((float*)sbw)[tid] = w;
    }
    __syncthreads();

    const int tx = tid & 15;   // b-group: 4 pairs at slots jp*16 + tx (conflict-free)
    const int ty = tid >> 4;   // a-group: 16 n rows ty*16 + i

    // b-side in registers: 4 packed pairs x 4 vars = 32 regs
    u64 bx2[4], by2[4], bz2[4], bw2[4];
#pragma unroll
    for (int jp = 0; jp < 4; jp++) {
        int s = jp * 16 + tx;
        bx2[jp] = sbx[s]; by2[jp] = sby[s]; bz2[jp] = sbz[s]; bw2[jp] = sbw[s];
    }

    const u64 NEG2 = 0xC0000000C0000000ULL;  // {-2.0f, -2.0f}
    float bst[8];
#pragma unroll
    for (int k = 0; k < 8; k++) bst[k] = 3.4028235e38f;

#pragma unroll 2
    for (int i = 0; i < 16; i++) {
        const int nn = ty * 16 + i;
        u64 ax = sax[nn], ay = say[nn], az = saz[nn], aw = saw[nn];
#pragma unroll
        for (int jp = 0; jp < 4; jp++) {
            u64 d = mul2(ax, bx2[jp]);
            d = fma2(ay, by2[jp], d);
            d = fma2(az, bz2[jp], d);
            u64 t  = add2(aw, bw2[jp]);
            u64 sq = fma2(NEG2, d, t);
            float lo, hi;
            unpack2(sq, lo, hi);
            bst[jp * 2 + 0] = fminf(bst[jp * 2 + 0], lo);
            bst[jp * 2 + 1] = fminf(bst[jp * 2 + 1], hi);
        }
    }
    float best = fminf(fminf(fminf(bst[0], bst[1]), fminf(bst[2], bst[3])),
                       fminf(fminf(bst[4], bst[5]), fminf(bst[6], bst[7])));

    // Warp reduce
#pragma unroll
    for (int off = 16; off; off >>= 1)
        best = fminf(best, __shfl_xor_sync(0xffffffffu, best, off));

    __shared__ float wmin[THREADS / 32];
    if ((tid & 31) == 0) wmin[tid >> 5] = best;
    __syncthreads();

    if (tid == 0) {
        float r = wmin[0];
#pragma unroll
        for (int w = 1; w < THREADS / 32; w++) r = fminf(r, wmin[w]);
        // nonneg float bits order as uint
        atomicMin(&g_minbits, __float_as_uint(fmaxf(r, 0.0f)));
        __threadfence();
        unsigned ticket = atomicAdd(&g_count, 1);
        if (ticket == (unsigned)(nblocks - 1)) {
            // last block: read-and-reset (deterministic across graph replays)
            unsigned bits = atomicExch(&g_minbits, FLT_MAX_BITS);
            atomicExch(&g_count, 0u);
            out[0] = sqrtf(__uint_as_float(bits));
        }
    }
}

extern "C" void kernel_launch(void* const* d_in, const int* in_sizes, int n_in,
                              void* d_out, int out_size) {
    const float* v1 = (const float*)d_in[0];
    const float* v2 = (const float*)d_in[1];
    float* out = (float*)d_out;

    const int B = 16;
    const int N = in_sizes[0] / (B * 3);
    const int M = in_sizes[1] / (B * 3);

    dim3 grid((M + TM - 1) / TM, (N + TN - 1) / TN, B);
    int nblocks = (int)(grid.x * grid.y * grid.z);

    pairmin_kernel<<<grid, THREADS>>>(v1, v2, B, N, M, nblocks, out);
}

// round 6
// speedup vs baseline: 1.2808x; 1.0234x over previous
#include <cuda_runtime.h>
#include <math.h>

// MinDistLoss: out = min_{b,n,m} sqrt(max( xx[b,n] + yy[b,m] - 2*dot(v1[b,n],v2[b,m]), 0 ))
//
// FROZEN numeric scheme (bit-exact vs reference, rel_err = 0.0 since round 1):
//   xx = (x0*x0 + x1*x1) + x2*x2         (separate mul/add)
//   dot = fma(z,z', fma(y,y', x*x'))     (ascending fma chain)
//   sq = fma(-2, dot, xx+yy)
// f32x2 packed ops round each half identically to scalar -> numerics unchanged.
//
// R6: multi-tile blocks. Each block stages a 256-n strip once, sweeps ~14
// m-tiles; next tile's global loads issued before the mainloop (latency hidden
// under compute). a-side in smem as ulonglong2 (LDS.128). b-tile in registers.

#define TN 256
#define TM 128
#define THREADS 256
#define MCHUNKS 4
#define FLT_MAX_BITS 0x7f7fffffu

__device__ unsigned g_minbits = FLT_MAX_BITS;
__device__ unsigned g_count   = 0;

typedef unsigned long long u64;

__device__ __forceinline__ u64 pack2(float lo, float hi) {
    u64 r; asm("mov.b64 %0, {%1, %2};" : "=l"(r) : "f"(lo), "f"(hi)); return r;
}
__device__ __forceinline__ void unpack2(u64 v, float& lo, float& hi) {
    asm("mov.b64 {%0, %1}, %2;" : "=f"(lo), "=f"(hi) : "l"(v));
}
__device__ __forceinline__ u64 mul2(u64 a, u64 b) {
    u64 r; asm("mul.rn.f32x2 %0, %1, %2;" : "=l"(r) : "l"(a), "l"(b)); return r;
}
__device__ __forceinline__ u64 add2(u64 a, u64 b) {
    u64 r; asm("add.rn.f32x2 %0, %1, %2;" : "=l"(r) : "l"(a), "l"(b)); return r;
}
__device__ __forceinline__ u64 fma2(u64 a, u64 b, u64 c) {
    u64 r; asm("fma.rn.f32x2 %0, %1, %2, %3;" : "=l"(r) : "l"(a), "l"(b), "l"(c)); return r;
}

__global__ __launch_bounds__(THREADS, 4)
void pairmin_kernel(const float* __restrict__ v1, const float* __restrict__ v2,
                    int B, int N, int M, int nblocks, float* __restrict__ out) {
    // a-strip: sa0[n] = {ax2, ay2}, sa1[n] = {az2, aw2}  (duplicated {v,v} pairs)
    // b-tile : sb0[p] = {bx2, by2}, sb1[p] = {bz2, bw2}  (natural {m,m+1} pairs)
    __shared__ ulonglong2 sa0[TN], sa1[TN];
    __shared__ ulonglong2 sb0[TM / 2], sb1[TM / 2];

    const int b     = blockIdx.z;
    const int n0    = blockIdx.y * TN;
    const int chunk = blockIdx.x;
    const float* p1 = v1 + (size_t)b * N * 3;
    const float* p2 = v2 + (size_t)b * M * 3;
    const int tid = threadIdx.x;
    const int MT  = (M + TM - 1) / TM;   // m-tiles total

    // ---- Stage a-strip once ----
    {
        int n = n0 + tid; if (n > N - 1) n = N - 1;
        float x0 = p1[n * 3 + 0], x1 = p1[n * 3 + 1], x2 = p1[n * 3 + 2];
        float w = __fadd_rn(__fadd_rn(__fmul_rn(x0, x0), __fmul_rn(x1, x1)),
                            __fmul_rn(x2, x2));
        sa0[tid] = make_ulonglong2(pack2(x0, x0), pack2(x1, x1));
        sa1[tid] = make_ulonglong2(pack2(x2, x2), pack2(w, w));
    }

    const int tx = tid & 15;   // b-group: 4 pairs at slots jp*16 + tx (conflict-free)
    const int ty = tid >> 4;   // a-group: 16 n rows ty*16 + i

    const u64 NEG2 = 0xC0000000C0000000ULL;  // {-2.0f, -2.0f}
    float bst[8];
#pragma unroll
    for (int k = 0; k < 8; k++) bst[k] = 3.4028235e38f;

    // ---- Prologue: stage first b-tile ----
    float gy0 = 0.f, gy1 = 0.f, gy2 = 0.f;
    int t0 = chunk;  // tiles: chunk, chunk+MCHUNKS, ...
    if (tid < TM && t0 < MT) {
        int m = t0 * TM + tid; if (m > M - 1) m = M - 1;
        gy0 = p2[m * 3 + 0]; gy1 = p2[m * 3 + 1]; gy2 = p2[m * 3 + 2];
    }
    if (tid < TM) {
        float w = __fadd_rn(__fadd_rn(__fmul_rn(gy0, gy0), __fmul_rn(gy1, gy1)),
                            __fmul_rn(gy2, gy2));
        float* f0 = (float*)sb0;   // pair p: [y0_lo, y0_hi, y1_lo, y1_hi]
        float* f1 = (float*)sb1;   // pair p: [y2_lo, y2_hi, w_lo,  w_hi ]
        int p = tid >> 1, h = tid & 1;
        f0[p * 4 + 0 + h] = gy0; f0[p * 4 + 2 + h] = gy1;
        f1[p * 4 + 0 + h] = gy2; f1[p * 4 + 2 + h] = w;
    }
    __syncthreads();

    for (int t = t0; t < MT; t += MCHUNKS) {
        // Load b-tile into compute registers
        u64 bx2[4], by2[4], bz2[4], bw2[4];
#pragma unroll
        for (int jp = 0; jp < 4; jp++) {
            int s = jp * 16 + tx;
            ulonglong2 B0 = sb0[s], B1 = sb1[s];
            bx2[jp] = B0.x; by2[jp] = B0.y; bz2[jp] = B1.x; bw2[jp] = B1.y;
        }

        // Issue next tile's global loads now (latency hidden under mainloop)
        int tn = t + MCHUNKS;
        if (tid < TM && tn < MT) {
            int m = tn * TM + tid; if (m > M - 1) m = M - 1;
            gy0 = p2[m * 3 + 0]; gy1 = p2[m * 3 + 1]; gy2 = p2[m * 3 + 2];
        }

        // ---- Mainloop over 16 a-rows ----
#pragma unroll 2
        for (int i = 0; i < 16; i++) {
            const int nn = ty * 16 + i;
            ulonglong2 A0 = sa0[nn], A1 = sa1[nn];
            const u64 ax = A0.x, ay = A0.y, az = A1.x, aw = A1.y;
#pragma unroll
            for (int jp = 0; jp < 4; jp++) {
                u64 d = mul2(ax, bx2[jp]);
                d = fma2(ay, by2[jp], d);
                d = fma2(az, bz2[jp], d);
                u64 tt = add2(aw, bw2[jp]);
                u64 sq = fma2(NEG2, d, tt);
                float lo, hi;
                unpack2(sq, lo, hi);
                bst[jp * 2 + 0] = fminf(bst[jp * 2 + 0], lo);
                bst[jp * 2 + 1] = fminf(bst[jp * 2 + 1], hi);
            }
        }

        if (tn < MT) {
            __syncthreads();   // everyone done reading sb for tile t
            if (tid < TM) {
                float w = __fadd_rn(__fadd_rn(__fmul_rn(gy0, gy0), __fmul_rn(gy1, gy1)),
                                    __fmul_rn(gy2, gy2));
                float* f0 = (float*)sb0;
                float* f1 = (float*)sb1;
                int p = tid >> 1, h = tid & 1;
                f0[p * 4 + 0 + h] = gy0; f0[p * 4 + 2 + h] = gy1;
                f1[p * 4 + 0 + h] = gy2; f1[p * 4 + 2 + h] = w;
            }
            __syncthreads();   // sb ready for tile t+MCHUNKS
        }
    }

    float best = fminf(fminf(fminf(bst[0], bst[1]), fminf(bst[2], bst[3])),
                       fminf(fminf(bst[4], bst[5]), fminf(bst[6], bst[7])));

    // Warp reduce
#pragma unroll
    for (int off = 16; off; off >>= 1)
        best = fminf(best, __shfl_xor_sync(0xffffffffu, best, off));

    __shared__ float wmin[THREADS / 32];
    if ((tid & 31) == 0) wmin[tid >> 5] = best;
    __syncthreads();

    if (tid == 0) {
        float r = wmin[0];
#pragma unroll
        for (int w = 1; w < THREADS / 32; w++) r = fminf(r, wmin[w]);
        atomicMin(&g_minbits, __float_as_uint(fmaxf(r, 0.0f)));
        __threadfence();
        unsigned ticket = atomicAdd(&g_count, 1);
        if (ticket == (unsigned)(nblocks - 1)) {
            // last block: read-and-reset (deterministic across graph replays)
            unsigned bits = atomicExch(&g_minbits, FLT_MAX_BITS);
            atomicExch(&g_count, 0u);
            out[0] = sqrtf(__uint_as_float(bits));
        }
    }
}

extern "C" void kernel_launch(void* const* d_in, const int* in_sizes, int n_in,
                              void* d_out, int out_size) {
    const float* v1 = (const float*)d_in[0];
    const float* v2 = (const float*)d_in[1];
    float* out = (float*)d_out;

    const int B = 16;
    const int N = in_sizes[0] / (B * 3);
    const int M = in_sizes[1] / (B * 3);

    dim3 grid(MCHUNKS, (N + TN - 1) / TN, B);
    int nblocks = (int)(grid.x * grid.y * grid.z);

    pairmin_kernel<<<grid, THREADS>>>(v1, v2, B, N, M, nblocks, out);
}